// round 1
// baseline (speedup 1.0000x reference)
#include <cuda_runtime.h>
#include <math.h>

#define B_  4
#define T_  2048
#define DH  512          // head dim == input dim
#define H_  8
#define ND  4096         // H*DH
#define BT  8192         // B*T

// ---------------- scratch (device globals: allocation-free) ----------------
__device__ float g_q[(size_t)BT * ND];            // 134 MB
__device__ float g_k[(size_t)BT * ND];            // 134 MB
__device__ float g_v[(size_t)BT * ND];            // 134 MB
__device__ float g_s[(size_t)B_ * H_ * T_ * T_];  // 537 MB

// =====================================================================
// Projection GEMM: C[BT,ND] = A[BT,DH] @ W[DH,ND] + bias
// 64x64 tile, BK=16, 256 threads, 4x4 microtile
// =====================================================================
__global__ __launch_bounds__(256) void proj_gemm(
    const float* __restrict__ A, const float* __restrict__ W,
    const float* __restrict__ bias, float* __restrict__ C)
{
    __shared__ float As[16][68];
    __shared__ float Bs[16][64];
    const int tid = threadIdx.x;
    const int m0 = blockIdx.y * 64, n0 = blockIdx.x * 64;
    const int ar = tid >> 2, ac = (tid & 3) * 4;    // A loader: 64 rows x 4 f4
    const int br = tid >> 4, bc = (tid & 15) * 4;   // B loader: 16 rows x 16 f4
    const int ty = tid >> 4, tx = tid & 15;

    float acc[4][4] = {};
    for (int k0 = 0; k0 < DH; k0 += 16) {
        float4 av = *(const float4*)(A + (size_t)(m0 + ar) * DH + k0 + ac);
        As[ac + 0][ar] = av.x; As[ac + 1][ar] = av.y;
        As[ac + 2][ar] = av.z; As[ac + 3][ar] = av.w;
        *(float4*)&Bs[br][bc] = *(const float4*)(W + (size_t)(k0 + br) * ND + n0 + bc);
        __syncthreads();
#pragma unroll
        for (int kk = 0; kk < 16; ++kk) {
            float a0 = As[kk][ty * 4 + 0], a1 = As[kk][ty * 4 + 1];
            float a2 = As[kk][ty * 4 + 2], a3 = As[kk][ty * 4 + 3];
            float b0 = Bs[kk][tx * 4 + 0], b1 = Bs[kk][tx * 4 + 1];
            float b2 = Bs[kk][tx * 4 + 2], b3 = Bs[kk][tx * 4 + 3];
            acc[0][0] += a0 * b0; acc[0][1] += a0 * b1; acc[0][2] += a0 * b2; acc[0][3] += a0 * b3;
            acc[1][0] += a1 * b0; acc[1][1] += a1 * b1; acc[1][2] += a1 * b2; acc[1][3] += a1 * b3;
            acc[2][0] += a2 * b0; acc[2][1] += a2 * b1; acc[2][2] += a2 * b2; acc[2][3] += a2 * b3;
            acc[3][0] += a3 * b0; acc[3][1] += a3 * b1; acc[3][2] += a3 * b2; acc[3][3] += a3 * b3;
        }
        __syncthreads();
    }
#pragma unroll
    for (int i = 0; i < 4; ++i) {
        int row = m0 + ty * 4 + i;
#pragma unroll
        for (int j = 0; j < 4; ++j) {
            int col = n0 + tx * 4 + j;
            C[(size_t)row * ND + col] = acc[i][j] + bias[col];
        }
    }
}

// =====================================================================
// Scores GEMM (NT): S[z,i,j] = SCALE * sum_d Q[b,i,h*DH+d] * K[b,j,h*DH+d]
// Causal tile-skip: tiles with tj > ti never computed (never read either).
// =====================================================================
__global__ __launch_bounds__(256) void scores_gemm(
    const float* __restrict__ Q, const float* __restrict__ Kp,
    float* __restrict__ S)
{
    const int ti = blockIdx.y, tj = blockIdx.x;
    if (tj > ti) return;                      // strictly above diagonal: skip
    const int z = blockIdx.z, b = z >> 3, h = z & 7;
    const float* A  = Q  + (size_t)b * T_ * ND + (size_t)h * DH;
    const float* Bp = Kp + (size_t)b * T_ * ND + (size_t)h * DH;
    float* Sz = S + (size_t)z * T_ * T_;

    __shared__ float As[16][68];
    __shared__ float Bs[16][68];
    const int tid = threadIdx.x;
    const int ar = tid >> 2, ac = (tid & 3) * 4;
    const int ty = tid >> 4, tx = tid & 15;
    const int m0 = ti * 64, n0 = tj * 64;

    float acc[4][4] = {};
    for (int k0 = 0; k0 < DH; k0 += 16) {
        float4 av = *(const float4*)(A + (size_t)(m0 + ar) * ND + k0 + ac);
        As[ac + 0][ar] = av.x; As[ac + 1][ar] = av.y;
        As[ac + 2][ar] = av.z; As[ac + 3][ar] = av.w;
        float4 bv = *(const float4*)(Bp + (size_t)(n0 + ar) * ND + k0 + ac);
        Bs[ac + 0][ar] = bv.x; Bs[ac + 1][ar] = bv.y;
        Bs[ac + 2][ar] = bv.z; Bs[ac + 3][ar] = bv.w;
        __syncthreads();
#pragma unroll
        for (int kk = 0; kk < 16; ++kk) {
            float a0 = As[kk][ty * 4 + 0], a1 = As[kk][ty * 4 + 1];
            float a2 = As[kk][ty * 4 + 2], a3 = As[kk][ty * 4 + 3];
            float b0 = Bs[kk][tx * 4 + 0], b1 = Bs[kk][tx * 4 + 1];
            float b2 = Bs[kk][tx * 4 + 2], b3 = Bs[kk][tx * 4 + 3];
            acc[0][0] += a0 * b0; acc[0][1] += a0 * b1; acc[0][2] += a0 * b2; acc[0][3] += a0 * b3;
            acc[1][0] += a1 * b0; acc[1][1] += a1 * b1; acc[1][2] += a1 * b2; acc[1][3] += a1 * b3;
            acc[2][0] += a2 * b0; acc[2][1] += a2 * b1; acc[2][2] += a2 * b2; acc[2][3] += a2 * b3;
            acc[3][0] += a3 * b0; acc[3][1] += a3 * b1; acc[3][2] += a3 * b2; acc[3][3] += a3 * b3;
        }
        __syncthreads();
    }
    const float scale = 0.044194173824159216f;  // 1/sqrt(512)
#pragma unroll
    for (int i = 0; i < 4; ++i) {
        int row = m0 + ty * 4 + i;
#pragma unroll
        for (int j = 0; j < 4; ++j)
            Sz[(size_t)row * T_ + n0 + tx * 4 + j] = acc[i][j] * scale;
    }
}

// =====================================================================
// Causal softmax, in place. One block per (z, row). Row cached in regs.
// exp(s - 1e9 - max) == 0 in fp32, so the masked tail is exactly zero
// in the reference too; we softmax the prefix [0, r] and zero-pad to
// the next 64 boundary (the only padding pv_gemm will read).
// =====================================================================
__global__ __launch_bounds__(256) void softmax_rows(float* __restrict__ S)
{
    const int r = blockIdx.x, z = blockIdx.y;
    float* row = S + ((size_t)z * T_ + r) * T_;
    const int L = r + 1;
    const int tid = threadIdx.x;

    float v[8];
    float m = -1e30f;
#pragma unroll
    for (int it = 0; it < 8; ++it) {
        int j = tid + it * 256;
        v[it] = (j < L) ? row[j] : -1e30f;
        m = fmaxf(m, v[it]);
    }
    __shared__ float red[256];
    red[tid] = m; __syncthreads();
    for (int s = 128; s > 0; s >>= 1) {
        if (tid < s) red[tid] = fmaxf(red[tid], red[tid + s]);
        __syncthreads();
    }
    m = red[0];
    __syncthreads();

    float sum = 0.f;
#pragma unroll
    for (int it = 0; it < 8; ++it) {
        int j = tid + it * 256;
        if (j < L) { v[it] = expf(v[it] - m); sum += v[it]; }
    }
    red[tid] = sum; __syncthreads();
    for (int s = 128; s > 0; s >>= 1) {
        if (tid < s) red[tid] += red[tid + s];
        __syncthreads();
    }
    const float inv = 1.0f / red[0];

#pragma unroll
    for (int it = 0; it < 8; ++it) {
        int j = tid + it * 256;
        if (j < L) row[j] = v[it] * inv;
    }
    const int Lpad = (L + 63) & ~63;
    for (int j = L + tid; j < Lpad; j += 256) row[j] = 0.f;
}

// =====================================================================
// P@V GEMM (NN): O[b,i,h*DH+d] = sum_j P[z,i,j] * V[b,j,h*DH+d]
// K-loop bounded at m0+64 (P columns beyond the tile's last row are 0).
// =====================================================================
__global__ __launch_bounds__(256) void pv_gemm(
    const float* __restrict__ P, const float* __restrict__ V,
    float* __restrict__ O)
{
    const int z = blockIdx.z, b = z >> 3, h = z & 7;
    const float* A  = P + (size_t)z * T_ * T_;                       // lda = T
    const float* Bp = V + (size_t)b * T_ * ND + (size_t)h * DH;      // ldb = ND
    float* C        = O + (size_t)b * T_ * ND + (size_t)h * DH;      // ldc = ND

    const int m0 = blockIdx.y * 64, n0 = blockIdx.x * 64;
    const int kmax = m0 + 64;                                        // causal bound

    __shared__ float As[16][68];
    __shared__ float Bs[16][64];
    const int tid = threadIdx.x;
    const int ar = tid >> 2, ac = (tid & 3) * 4;
    const int br = tid >> 4, bc = (tid & 15) * 4;
    const int ty = tid >> 4, tx = tid & 15;

    float acc[4][4] = {};
    for (int k0 = 0; k0 < kmax; k0 += 16) {
        float4 av = *(const float4*)(A + (size_t)(m0 + ar) * T_ + k0 + ac);
        As[ac + 0][ar] = av.x; As[ac + 1][ar] = av.y;
        As[ac + 2][ar] = av.z; As[ac + 3][ar] = av.w;
        *(float4*)&Bs[br][bc] = *(const float4*)(Bp + (size_t)(k0 + br) * ND + n0 + bc);
        __syncthreads();
#pragma unroll
        for (int kk = 0; kk < 16; ++kk) {
            float a0 = As[kk][ty * 4 + 0], a1 = As[kk][ty * 4 + 1];
            float a2 = As[kk][ty * 4 + 2], a3 = As[kk][ty * 4 + 3];
            float b0 = Bs[kk][tx * 4 + 0], b1 = Bs[kk][tx * 4 + 1];
            float b2 = Bs[kk][tx * 4 + 2], b3 = Bs[kk][tx * 4 + 3];
            acc[0][0] += a0 * b0; acc[0][1] += a0 * b1; acc[0][2] += a0 * b2; acc[0][3] += a0 * b3;
            acc[1][0] += a1 * b0; acc[1][1] += a1 * b1; acc[1][2] += a1 * b2; acc[1][3] += a1 * b3;
            acc[2][0] += a2 * b0; acc[2][1] += a2 * b1; acc[2][2] += a2 * b2; acc[2][3] += a2 * b3;
            acc[3][0] += a3 * b0; acc[3][1] += a3 * b1; acc[3][2] += a3 * b2; acc[3][3] += a3 * b3;
        }
        __syncthreads();
    }
#pragma unroll
    for (int i = 0; i < 4; ++i) {
        int row = m0 + ty * 4 + i;
#pragma unroll
        for (int j = 0; j < 4; ++j)
            C[(size_t)row * ND + n0 + tx * 4 + j] = acc[i][j];
    }
}

// =====================================================================
extern "C" void kernel_launch(void* const* d_in, const int* in_sizes, int n_in,
                              void* d_out, int out_size)
{
    const float* query = (const float*)d_in[0];
    const float* value = (const float*)d_in[1];
    const float* Wq    = (const float*)d_in[2];
    const float* bq    = (const float*)d_in[3];
    const float* Wk    = (const float*)d_in[4];
    const float* bk    = (const float*)d_in[5];
    const float* Wv    = (const float*)d_in[6];
    const float* bv    = (const float*)d_in[7];
    float* out = (float*)d_out;

    float *q, *k, *v, *s;
    cudaGetSymbolAddress((void**)&q, g_q);
    cudaGetSymbolAddress((void**)&k, g_k);
    cudaGetSymbolAddress((void**)&v, g_v);
    cudaGetSymbolAddress((void**)&s, g_s);

    dim3 blk(256);

    dim3 gproj(ND / 64, BT / 64);
    proj_gemm<<<gproj, blk>>>(query, Wq, bq, q);
    proj_gemm<<<gproj, blk>>>(value, Wk, bk, k);
    proj_gemm<<<gproj, blk>>>(value, Wv, bv, v);

    dim3 gs(T_ / 64, T_ / 64, B_ * H_);
    scores_gemm<<<gs, blk>>>(q, k, s);

    dim3 gsm(T_, B_ * H_);
    softmax_rows<<<gsm, blk>>>(s);

    dim3 gpv(DH / 64, T_ / 64, B_ * H_);
    pv_gemm<<<gpv, blk>>>(s, v, out);
}

// round 3
// speedup vs baseline: 3.2586x; 3.2586x over previous
#include <cuda_runtime.h>
#include <math.h>
#include <cstdint>

#define B_  4
#define T_  2048
#define DH  512
#define H_  8
#define ND  4096
#define BT  8192
#define TM  128
#define TN  128
#define KC  32          // K floats per smem chunk
#define SPAD 36         // smem row pitch (banks: (4m+k)%32 all distinct)

// ---------------- scratch (device globals: allocation-free) ----------------
__device__ float g_q [(size_t)BT * ND];             // 134 MB
__device__ float g_k [(size_t)BT * ND];             // 134 MB
__device__ float g_vt[(size_t)B_ * ND * T_];        // 134 MB  [b][h*DH+d][t]
__device__ float g_s [(size_t)B_ * H_ * T_ * T_];   // 537 MB
__device__ float g_wt[3 * (size_t)ND * DH];         // 25 MB   W^T: [n][k]

__device__ __forceinline__ uint32_t f2tf32(float x) {
    uint32_t o;
    asm("cvt.rna.tf32.f32 %0, %1;" : "=r"(o) : "f"(x));
    return o;
}

__device__ __forceinline__ void mma_tf32(float& c0, float& c1, float& c2, float& c3,
                                         uint32_t a0, uint32_t a1, uint32_t a2, uint32_t a3,
                                         uint32_t b0, uint32_t b1) {
    asm volatile("mma.sync.aligned.m16n8k8.row.col.f32.tf32.tf32.f32 "
                 "{%0,%1,%2,%3}, {%4,%5,%6,%7}, {%8,%9}, {%0,%1,%2,%3};"
                 : "+f"(c0), "+f"(c1), "+f"(c2), "+f"(c3)
                 : "r"(a0), "r"(a1), "r"(a2), "r"(a3), "r"(b0), "r"(b1));
}

// ======================= generic tf32 mma.sync GEMM =======================
// C[m][n] = scale * sum_k A[m][k] * B[n][k]  (+bias)   (both operands K-major)
struct GemmArgs {
    const float* A; long long sAz, sAh; int lda;
    const float* B; long long sBz, sBh; int ldb;
    float*       C; long long sCz, sCh; int ldc;
    int K; int zHeads;
    const float* bias; int biasMode;   // 0 none, 1 by-col, 2 by-row
    float scale;
    int causal;                        // 0 none, 1 skip tj>ti, 2 kmax=m0+TM
};

__global__ __launch_bounds__(256) void gemm_tc(GemmArgs ga)
{
    const int ti = blockIdx.y, tj = blockIdx.x, z = blockIdx.z;
    if (ga.causal == 1 && tj > ti) return;

    extern __shared__ uint32_t smem[];
    uint32_t (*As)[SPAD] = (uint32_t(*)[SPAD])smem;
    uint32_t (*Bs)[SPAD] = (uint32_t(*)[SPAD])(smem + TM * SPAD);

    const int tid  = threadIdx.x;
    const int wid  = tid >> 5, lane = tid & 31;
    const int wm   = wid >> 2, wn = wid & 3;        // 2 x 4 warp grid
    const int gid  = lane >> 2, tig = lane & 3;
    const int m0 = ti * TM, n0 = tj * TN;

    int kmax = ga.K;
    if (ga.causal == 2) kmax = min(kmax, m0 + TM);
    const int NC = kmax / KC;

    const int zb = z / ga.zHeads, zh = z - zb * ga.zHeads;
    const float* Ag = ga.A + (size_t)zb * ga.sAz + (size_t)zh * ga.sAh;
    const float* Bg = ga.B + (size_t)zb * ga.sBz + (size_t)zh * ga.sBh;

    // gmem loader mapping: 4 iters, each 32 rows x 8 float4
    const int lr = tid >> 3, lc = (tid & 7) * 4;

    float4 pa[4], pb[4];
#pragma unroll
    for (int i = 0; i < 4; ++i) {
        pa[i] = *(const float4*)(Ag + (size_t)(m0 + lr + i * 32) * ga.lda + lc);
        pb[i] = *(const float4*)(Bg + (size_t)(n0 + lr + i * 32) * ga.ldb + lc);
    }

    float acc[4][4][4];
#pragma unroll
    for (int mt = 0; mt < 4; ++mt)
#pragma unroll
        for (int nt = 0; nt < 4; ++nt)
#pragma unroll
            for (int r = 0; r < 4; ++r) acc[mt][nt][r] = 0.f;

    for (int c = 0; c < NC; ++c) {
#pragma unroll
        for (int i = 0; i < 4; ++i) {
            uint32_t* pA = &As[lr + i * 32][lc];
            pA[0] = f2tf32(pa[i].x); pA[1] = f2tf32(pa[i].y);
            pA[2] = f2tf32(pa[i].z); pA[3] = f2tf32(pa[i].w);
            uint32_t* pB = &Bs[lr + i * 32][lc];
            pB[0] = f2tf32(pb[i].x); pB[1] = f2tf32(pb[i].y);
            pB[2] = f2tf32(pb[i].z); pB[3] = f2tf32(pb[i].w);
        }
        __syncthreads();

        if (c + 1 < NC) {
            const int k0 = (c + 1) * KC;
#pragma unroll
            for (int i = 0; i < 4; ++i) {
                pa[i] = *(const float4*)(Ag + (size_t)(m0 + lr + i * 32) * ga.lda + k0 + lc);
                pb[i] = *(const float4*)(Bg + (size_t)(n0 + lr + i * 32) * ga.ldb + k0 + lc);
            }
        }

#pragma unroll
        for (int ks = 0; ks < 4; ++ks) {
            const int k = ks * 8;
            uint32_t a[4][4], b[4][2];
#pragma unroll
            for (int mt = 0; mt < 4; ++mt) {
                const int m = wm * 64 + mt * 16 + gid;
                a[mt][0] = As[m][k + tig];
                a[mt][1] = As[m + 8][k + tig];
                a[mt][2] = As[m][k + tig + 4];
                a[mt][3] = As[m + 8][k + tig + 4];
            }
#pragma unroll
            for (int nt = 0; nt < 4; ++nt) {
                const int n = wn * 32 + nt * 8 + gid;
                b[nt][0] = Bs[n][k + tig];
                b[nt][1] = Bs[n][k + tig + 4];
            }
#pragma unroll
            for (int mt = 0; mt < 4; ++mt)
#pragma unroll
                for (int nt = 0; nt < 4; ++nt)
                    mma_tf32(acc[mt][nt][0], acc[mt][nt][1], acc[mt][nt][2], acc[mt][nt][3],
                             a[mt][0], a[mt][1], a[mt][2], a[mt][3],
                             b[nt][0], b[nt][1]);
        }
        __syncthreads();
    }

    // ---------------- epilogue ----------------
    float* Cb = ga.C + (size_t)zb * ga.sCz + (size_t)zh * ga.sCh;
#pragma unroll
    for (int mt = 0; mt < 4; ++mt) {
        const int row0 = m0 + wm * 64 + mt * 16 + gid;
#pragma unroll
        for (int nt = 0; nt < 4; ++nt) {
            const int col = n0 + wn * 32 + nt * 8 + tig * 2;
            float ba0 = 0.f, ba1 = 0.f, bb0 = 0.f, bb1 = 0.f;
            if (ga.biasMode == 1) {
                ba0 = bb0 = ga.bias[col];
                ba1 = bb1 = ga.bias[col + 1];
            } else if (ga.biasMode == 2) {
                ba0 = ba1 = ga.bias[row0];
                bb0 = bb1 = ga.bias[row0 + 8];
            }
            float2 v0, v1;
            v0.x = acc[mt][nt][0] * ga.scale + ba0;
            v0.y = acc[mt][nt][1] * ga.scale + ba1;
            v1.x = acc[mt][nt][2] * ga.scale + bb0;
            v1.y = acc[mt][nt][3] * ga.scale + bb1;
            *(float2*)(Cb + (size_t)row0 * ga.ldc + col) = v0;
            *(float2*)(Cb + (size_t)(row0 + 8) * ga.ldc + col) = v1;
        }
    }
}

// ======================= W transpose: Wt[n][k] = W[k][n] =======================
__global__ __launch_bounds__(256) void transpose_w(
    const float* __restrict__ W0, const float* __restrict__ W1,
    const float* __restrict__ W2, float* __restrict__ Wt)
{
    __shared__ float t[32][33];
    const float* W = (blockIdx.z == 0) ? W0 : (blockIdx.z == 1) ? W1 : W2;
    float* O = Wt + (size_t)blockIdx.z * ND * DH;
    const int x0 = blockIdx.x * 32;   // n
    const int y0 = blockIdx.y * 32;   // k
    const int tx = threadIdx.x, ty = threadIdx.y;
#pragma unroll
    for (int i = 0; i < 32; i += 8)
        t[ty + i][tx] = W[(size_t)(y0 + ty + i) * ND + x0 + tx];
    __syncthreads();
#pragma unroll
    for (int i = 0; i < 32; i += 8)
        O[(size_t)(x0 + ty + i) * DH + y0 + tx] = t[tx][ty + i];
}

// ======================= causal softmax (pad to 128) =======================
__global__ __launch_bounds__(256) void softmax_rows(float* __restrict__ S)
{
    const int r = blockIdx.x, z = blockIdx.y;
    float* row = S + ((size_t)z * T_ + r) * T_;
    const int L = r + 1;
    const int tid = threadIdx.x;

    float v[8];
    float m = -1e30f;
#pragma unroll
    for (int it = 0; it < 8; ++it) {
        int j = tid + it * 256;
        v[it] = (j < L) ? row[j] : -1e30f;
        m = fmaxf(m, v[it]);
    }
    __shared__ float red[256];
    red[tid] = m; __syncthreads();
    for (int s = 128; s > 0; s >>= 1) {
        if (tid < s) red[tid] = fmaxf(red[tid], red[tid + s]);
        __syncthreads();
    }
    m = red[0];
    __syncthreads();

    float sum = 0.f;
#pragma unroll
    for (int it = 0; it < 8; ++it) {
        int j = tid + it * 256;
        if (j < L) { v[it] = expf(v[it] - m); sum += v[it]; }
    }
    red[tid] = sum; __syncthreads();
    for (int s = 128; s > 0; s >>= 1) {
        if (tid < s) red[tid] += red[tid + s];
        __syncthreads();
    }
    const float inv = 1.0f / red[0];

#pragma unroll
    for (int it = 0; it < 8; ++it) {
        int j = tid + it * 256;
        if (j < L) row[j] = v[it] * inv;
    }
    const int Lpad = (L + 127) & ~127;   // zero junk in diagonal 128-tile
    for (int j = L + tid; j < Lpad; j += 256) row[j] = 0.f;
}

// =====================================================================
extern "C" void kernel_launch(void* const* d_in, const int* in_sizes, int n_in,
                              void* d_out, int out_size)
{
    const float* query = (const float*)d_in[0];
    const float* value = (const float*)d_in[1];
    const float* Wq    = (const float*)d_in[2];
    const float* bq    = (const float*)d_in[3];
    const float* Wk    = (const float*)d_in[4];
    const float* bk    = (const float*)d_in[5];
    const float* Wv    = (const float*)d_in[6];
    const float* bv    = (const float*)d_in[7];
    float* out = (float*)d_out;

    float *q, *k, *vt, *s, *wt;
    cudaGetSymbolAddress((void**)&q,  g_q);
    cudaGetSymbolAddress((void**)&k,  g_k);
    cudaGetSymbolAddress((void**)&vt, g_vt);
    cudaGetSymbolAddress((void**)&s,  g_s);
    cudaGetSymbolAddress((void**)&wt, g_wt);

    const int SMEM_BYTES = 2 * TM * SPAD * 4;   // 36864
    cudaFuncSetAttribute(gemm_tc, cudaFuncAttributeMaxDynamicSharedMemorySize, SMEM_BYTES);

    // 0. transpose the three weight matrices
    transpose_w<<<dim3(ND / 32, DH / 32, 3), dim3(32, 8)>>>(Wq, Wk, Wv, wt);

    GemmArgs a;

    // 1. q = query @ Wq + bq          [8192, 4096]
    a = { query, 0, 0, DH,
          wt + 0 * (size_t)ND * DH, 0, 0, DH,
          q, 0, 0, ND,
          DH, 1, bq, 1, 1.0f, 0 };
    gemm_tc<<<dim3(ND / TN, BT / TM, 1), 256, SMEM_BYTES>>>(a);

    // 2. k = value @ Wk + bk          [8192, 4096]
    a = { value, 0, 0, DH,
          wt + 1 * (size_t)ND * DH, 0, 0, DH,
          k, 0, 0, ND,
          DH, 1, bk, 1, 1.0f, 0 };
    gemm_tc<<<dim3(ND / TN, BT / TM, 1), 256, SMEM_BYTES>>>(a);

    // 3. vt[b][m][t] = (Wv^T @ value_b^T)[m][t] + bv[m]   M=ND, N=T, per batch
    a = { wt + 2 * (size_t)ND * DH, 0, 0, DH,
          value, (long long)T_ * DH, 0, DH,
          vt, (long long)ND * T_, 0, T_,
          DH, 1, bv, 2, 1.0f, 0 };
    gemm_tc<<<dim3(T_ / TN, ND / TM, B_), 256, SMEM_BYTES>>>(a);

    // 4. scores[z] = scale * q_z @ k_z^T   (causal tile skip)
    a = { q, (long long)T_ * ND, DH, ND,
          k, (long long)T_ * ND, DH, ND,
          s, 8LL * T_ * T_, (long long)T_ * T_, T_,
          DH, H_, nullptr, 0, 0.044194173824159216f, 1 };
    gemm_tc<<<dim3(T_ / TN, T_ / TM, B_ * H_), 256, SMEM_BYTES>>>(a);

    // 5. softmax rows (causal, pad to 128)
    softmax_rows<<<dim3(T_, B_ * H_), 256>>>(s);

    // 6. out[b,i,h*DH+d] = sum_j P[z,i,j] * vt[b, h*DH+d, j]  (K bounded)
    a = { s, 8LL * T_ * T_, (long long)T_ * T_, T_,
          vt, (long long)ND * T_, (long long)DH * T_, T_,
          out, (long long)T_ * ND, DH, ND,
          T_, H_, nullptr, 0, 1.0f, 2 };
    gemm_tc<<<dim3(DH / TN, T_ / TM, B_ * H_), 256, SMEM_BYTES>>>(a);
}

// round 4
// speedup vs baseline: 4.1889x; 1.2855x over previous
#include <cuda_runtime.h>
#include <math.h>
#include <cstdint>

#define B_  4
#define T_  2048
#define DH  512
#define H_  8
#define ND  4096
#define BT  8192
#define TM  128
#define TN  128
#define KC  32
#define SPAD 36                          // padded row pitch (conflict-free frags)
#define STAGE_U32 (2 * TM * SPAD)        // A+B floats per stage
#define SMEM_BYTES (2 * STAGE_U32 * 4)   // 2 stages = 73728 B

// ---------------- scratch (device globals: allocation-free) ----------------
__device__ float g_q [(size_t)BT * ND];             // 134 MB (tf32-rounded)
__device__ float g_k [(size_t)BT * ND];             // 134 MB (tf32-rounded)
__device__ float g_vt[(size_t)B_ * ND * T_];        // 134 MB (tf32-rounded)
__device__ float g_s [(size_t)B_ * H_ * T_ * T_];   // 537 MB
__device__ float g_wt[3 * (size_t)ND * DH];         // 25 MB  W^T (tf32-rounded)
__device__ float g_qr[(size_t)BT * DH];             // 17 MB  query (tf32-rounded)
__device__ float g_vr[(size_t)BT * DH];             // 17 MB  value (tf32-rounded)

__device__ __forceinline__ uint32_t f2tf32(float x) {
    uint32_t o;
    asm("cvt.rna.tf32.f32 %0, %1;" : "=r"(o) : "f"(x));
    return o;
}
__device__ __forceinline__ uint32_t smem_u32(const void* p) {
    uint32_t a;
    asm("{ .reg .u64 t; cvta.to.shared.u64 t, %1; cvt.u32.u64 %0, t; }"
        : "=r"(a) : "l"(p));
    return a;
}
__device__ __forceinline__ void cp_async16(uint32_t saddr, const float* gaddr) {
    asm volatile("cp.async.cg.shared.global [%0], [%1], 16;"
                 :: "r"(saddr), "l"(gaddr));
}
#define CP_COMMIT() asm volatile("cp.async.commit_group;" ::: "memory")
#define CP_WAIT1()  asm volatile("cp.async.wait_group 1;" ::: "memory")
#define CP_WAIT0()  asm volatile("cp.async.wait_group 0;" ::: "memory")

__device__ __forceinline__ void mma_tf32(float& c0, float& c1, float& c2, float& c3,
                                         uint32_t a0, uint32_t a1, uint32_t a2, uint32_t a3,
                                         uint32_t b0, uint32_t b1) {
    asm volatile("mma.sync.aligned.m16n8k8.row.col.f32.tf32.tf32.f32 "
                 "{%0,%1,%2,%3}, {%4,%5,%6,%7}, {%8,%9}, {%0,%1,%2,%3};"
                 : "+f"(c0), "+f"(c1), "+f"(c2), "+f"(c3)
                 : "r"(a0), "r"(a1), "r"(a2), "r"(a3), "r"(b0), "r"(b1));
}

// ======================= generic tf32 mma.sync GEMM =======================
// C[m][n] = scale * sum_k A[m][k] * B[n][k]  (+bias)  — operands tf32-prerounded
struct GemmArgs {
    const float* A; long long sAz, sAh; int lda;
    const float* B; long long sBz, sBh; int ldb;
    float*       C; long long sCz, sCh; int ldc;
    int K; int zHeads;
    const float* bias; int biasMode;   // 0 none, 1 by-col, 2 by-row
    float scale;
    int causal;                        // 0 none, 1 skip tj>ti, 2 kmax=m0+TM
    int roundC;                        // round outputs to tf32 (intermediates)
};

__global__ __launch_bounds__(256, 2) void gemm_tc(GemmArgs ga)
{
    const int ti = blockIdx.y, tj = blockIdx.x, z = blockIdx.z;
    if (ga.causal == 1 && tj > ti) return;

    extern __shared__ uint32_t smem[];
    const uint32_t sb = smem_u32(smem);

    const int tid  = threadIdx.x;
    const int wid  = tid >> 5, lane = tid & 31;
    const int wm   = wid >> 2, wn = wid & 3;        // 2 x 4 warp grid
    const int gid  = lane >> 2, tig = lane & 3;
    const int m0 = ti * TM, n0 = tj * TN;

    int kmax = ga.K;
    if (ga.causal == 2) kmax = min(kmax, m0 + TM);
    const int NC = kmax / KC;

    const int zb = z / ga.zHeads, zh = z - zb * ga.zHeads;
    const float* Ag = ga.A + (size_t)zb * ga.sAz + (size_t)zh * ga.sAh;
    const float* Bg = ga.B + (size_t)zb * ga.sBz + (size_t)zh * ga.sBh;

    // loader mapping: 4 chunks/thread per matrix per stage (16B each)
    int lrow[4], soff[4];
    const float *pA[4], *pB[4];
#pragma unroll
    for (int i = 0; i < 4; ++i) {
        const int id = i * 256 + tid;
        const int row = id >> 3, kc = (id & 7) * 4;
        lrow[i] = row;
        soff[i] = (row * SPAD + kc) * 4;
        pA[i] = Ag + (size_t)(m0 + row) * ga.lda + kc;
        pB[i] = Bg + (size_t)(n0 + row) * ga.ldb + kc;
    }

#define ISSUE(c) do {                                                   \
        const int _buf = (c) & 1;                                       \
        const uint32_t _sA = sb + _buf * (STAGE_U32 * 4);               \
        const uint32_t _sB = _sA + TM * SPAD * 4;                       \
        const int _k0 = (c) * KC;                                       \
        _Pragma("unroll")                                               \
        for (int _i = 0; _i < 4; ++_i) {                                \
            cp_async16(_sA + soff[_i], pA[_i] + _k0);                   \
            cp_async16(_sB + soff[_i], pB[_i] + _k0);                   \
        }                                                               \
        CP_COMMIT();                                                    \
    } while (0)

    float acc[4][4][4];
#pragma unroll
    for (int mt = 0; mt < 4; ++mt)
#pragma unroll
        for (int nt = 0; nt < 4; ++nt)
#pragma unroll
            for (int r = 0; r < 4; ++r) acc[mt][nt][r] = 0.f;

    ISSUE(0);

    for (int c = 0; c < NC; ++c) {
        if (c + 1 < NC) { ISSUE(c + 1); CP_WAIT1(); }
        else            { CP_WAIT0(); }
        __syncthreads();

        const uint32_t* Sbase = smem + (c & 1) * STAGE_U32;
        const uint32_t (*As)[SPAD] = (const uint32_t(*)[SPAD])Sbase;
        const uint32_t (*Bs)[SPAD] = (const uint32_t(*)[SPAD])(Sbase + TM * SPAD);

#pragma unroll
        for (int ks = 0; ks < 4; ++ks) {
            const int k = ks * 8;
            uint32_t a[4][4], b[4][2];
#pragma unroll
            for (int mt = 0; mt < 4; ++mt) {
                const int m = wm * 64 + mt * 16 + gid;
                a[mt][0] = As[m][k + tig];
                a[mt][1] = As[m + 8][k + tig];
                a[mt][2] = As[m][k + tig + 4];
                a[mt][3] = As[m + 8][k + tig + 4];
            }
#pragma unroll
            for (int nt = 0; nt < 4; ++nt) {
                const int n = wn * 32 + nt * 8 + gid;
                b[nt][0] = Bs[n][k + tig];
                b[nt][1] = Bs[n][k + tig + 4];
            }
#pragma unroll
            for (int mt = 0; mt < 4; ++mt)
#pragma unroll
                for (int nt = 0; nt < 4; ++nt)
                    mma_tf32(acc[mt][nt][0], acc[mt][nt][1], acc[mt][nt][2], acc[mt][nt][3],
                             a[mt][0], a[mt][1], a[mt][2], a[mt][3],
                             b[nt][0], b[nt][1]);
        }
        __syncthreads();
    }

    // ---------------- epilogue ----------------
    float* Cb = ga.C + (size_t)zb * ga.sCz + (size_t)zh * ga.sCh;
#pragma unroll
    for (int mt = 0; mt < 4; ++mt) {
        const int row0 = m0 + wm * 64 + mt * 16 + gid;
#pragma unroll
        for (int nt = 0; nt < 4; ++nt) {
            const int col = n0 + wn * 32 + nt * 8 + tig * 2;
            float ba0 = 0.f, ba1 = 0.f, bb0 = 0.f, bb1 = 0.f;
            if (ga.biasMode == 1) {
                ba0 = bb0 = ga.bias[col];
                ba1 = bb1 = ga.bias[col + 1];
            } else if (ga.biasMode == 2) {
                ba0 = ba1 = ga.bias[row0];
                bb0 = bb1 = ga.bias[row0 + 8];
            }
            float2 v0, v1;
            v0.x = acc[mt][nt][0] * ga.scale + ba0;
            v0.y = acc[mt][nt][1] * ga.scale + ba1;
            v1.x = acc[mt][nt][2] * ga.scale + bb0;
            v1.y = acc[mt][nt][3] * ga.scale + bb1;
            if (ga.roundC) {
                v0.x = __uint_as_float(f2tf32(v0.x));
                v0.y = __uint_as_float(f2tf32(v0.y));
                v1.x = __uint_as_float(f2tf32(v1.x));
                v1.y = __uint_as_float(f2tf32(v1.y));
            }
            *(float2*)(Cb + (size_t)row0 * ga.ldc + col) = v0;
            *(float2*)(Cb + (size_t)(row0 + 8) * ga.ldc + col) = v1;
        }
    }
#undef ISSUE
}

// =============== round-copy: out[i] = tf32(in[i]) ===============
__global__ __launch_bounds__(256) void round_copy(
    const float* __restrict__ in, float* __restrict__ out, int n4)
{
    const int i = blockIdx.x * 256 + threadIdx.x;
    if (i < n4) {
        float4 v = ((const float4*)in)[i];
        v.x = __uint_as_float(f2tf32(v.x));
        v.y = __uint_as_float(f2tf32(v.y));
        v.z = __uint_as_float(f2tf32(v.z));
        v.w = __uint_as_float(f2tf32(v.w));
        ((float4*)out)[i] = v;
    }
}

// ======== W transpose + round: Wt[n][k] = tf32(W[k][n]) ========
__global__ __launch_bounds__(256) void transpose_w(
    const float* __restrict__ W0, const float* __restrict__ W1,
    const float* __restrict__ W2, float* __restrict__ Wt)
{
    __shared__ float t[32][33];
    const float* W = (blockIdx.z == 0) ? W0 : (blockIdx.z == 1) ? W1 : W2;
    float* O = Wt + (size_t)blockIdx.z * ND * DH;
    const int x0 = blockIdx.x * 32;   // n
    const int y0 = blockIdx.y * 32;   // k
    const int tx = threadIdx.x, ty = threadIdx.y;
#pragma unroll
    for (int i = 0; i < 32; i += 8)
        t[ty + i][tx] = W[(size_t)(y0 + ty + i) * ND + x0 + tx];
    __syncthreads();
#pragma unroll
    for (int i = 0; i < 32; i += 8)
        O[(size_t)(x0 + ty + i) * DH + y0 + tx] = __uint_as_float(f2tf32(t[tx][ty + i]));
}

// ======================= causal softmax (pad to 128, tf32 probs) =======================
__global__ __launch_bounds__(256) void softmax_rows(float* __restrict__ S)
{
    const int r = blockIdx.x, z = blockIdx.y;
    float* row = S + ((size_t)z * T_ + r) * T_;
    const int L = r + 1;
    const int tid = threadIdx.x;

    float v[8];
    float m = -1e30f;
#pragma unroll
    for (int it = 0; it < 8; ++it) {
        int j = tid + it * 256;
        v[it] = (j < L) ? row[j] : -1e30f;
        m = fmaxf(m, v[it]);
    }
    __shared__ float red[256];
    red[tid] = m; __syncthreads();
    for (int s = 128; s > 0; s >>= 1) {
        if (tid < s) red[tid] = fmaxf(red[tid], red[tid + s]);
        __syncthreads();
    }
    m = red[0];
    __syncthreads();

    float sum = 0.f;
#pragma unroll
    for (int it = 0; it < 8; ++it) {
        int j = tid + it * 256;
        if (j < L) { v[it] = expf(v[it] - m); sum += v[it]; }
    }
    red[tid] = sum; __syncthreads();
    for (int s = 128; s > 0; s >>= 1) {
        if (tid < s) red[tid] += red[tid + s];
        __syncthreads();
    }
    const float inv = 1.0f / red[0];

#pragma unroll
    for (int it = 0; it < 8; ++it) {
        int j = tid + it * 256;
        if (j < L) row[j] = __uint_as_float(f2tf32(v[it] * inv));
    }
    const int Lpad = (L + 127) & ~127;   // zero junk in diagonal 128-tile
    for (int j = L + tid; j < Lpad; j += 256) row[j] = 0.f;
}

// =====================================================================
extern "C" void kernel_launch(void* const* d_in, const int* in_sizes, int n_in,
                              void* d_out, int out_size)
{
    const float* query = (const float*)d_in[0];
    const float* value = (const float*)d_in[1];
    const float* Wq    = (const float*)d_in[2];
    const float* bq    = (const float*)d_in[3];
    const float* Wk    = (const float*)d_in[4];
    const float* bk    = (const float*)d_in[5];
    const float* Wv    = (const float*)d_in[6];
    const float* bv    = (const float*)d_in[7];
    float* out = (float*)d_out;

    float *q, *k, *vt, *s, *wt, *qr, *vr;
    cudaGetSymbolAddress((void**)&q,  g_q);
    cudaGetSymbolAddress((void**)&k,  g_k);
    cudaGetSymbolAddress((void**)&vt, g_vt);
    cudaGetSymbolAddress((void**)&s,  g_s);
    cudaGetSymbolAddress((void**)&wt, g_wt);
    cudaGetSymbolAddress((void**)&qr, g_qr);
    cudaGetSymbolAddress((void**)&vr, g_vr);

    cudaFuncSetAttribute(gemm_tc, cudaFuncAttributeMaxDynamicSharedMemorySize, SMEM_BYTES);

    // 0. pre-round inputs + transpose/round weights
    const int n4 = BT * DH / 4;
    round_copy<<<n4 / 256, 256>>>(query, qr, n4);
    round_copy<<<n4 / 256, 256>>>(value, vr, n4);
    transpose_w<<<dim3(ND / 32, DH / 32, 3), dim3(32, 8)>>>(Wq, Wk, Wv, wt);

    GemmArgs a;

    // 1. q = query @ Wq + bq          [8192, 4096]   (tf32-rounded out)
    a = { qr, 0, 0, DH,
          wt + 0 * (size_t)ND * DH, 0, 0, DH,
          q, 0, 0, ND,
          DH, 1, bq, 1, 1.0f, 0, 1 };
    gemm_tc<<<dim3(ND / TN, BT / TM, 1), 256, SMEM_BYTES>>>(a);

    // 2. k = value @ Wk + bk          [8192, 4096]   (tf32-rounded out)
    a = { vr, 0, 0, DH,
          wt + 1 * (size_t)ND * DH, 0, 0, DH,
          k, 0, 0, ND,
          DH, 1, bk, 1, 1.0f, 0, 1 };
    gemm_tc<<<dim3(ND / TN, BT / TM, 1), 256, SMEM_BYTES>>>(a);

    // 3. vt[b][m][t] = (Wv^T @ value_b^T)[m][t] + bv[m]   (tf32-rounded out)
    a = { wt + 2 * (size_t)ND * DH, 0, 0, DH,
          vr, (long long)T_ * DH, 0, DH,
          vt, (long long)ND * T_, 0, T_,
          DH, 1, bv, 2, 1.0f, 0, 1 };
    gemm_tc<<<dim3(T_ / TN, ND / TM, B_), 256, SMEM_BYTES>>>(a);

    // 4. scores[z] = scale * q_z @ k_z^T   (causal tile skip)
    a = { q, (long long)T_ * ND, DH, ND,
          k, (long long)T_ * ND, DH, ND,
          s, 8LL * T_ * T_, (long long)T_ * T_, T_,
          DH, H_, nullptr, 0, 0.044194173824159216f, 1, 0 };
    gemm_tc<<<dim3(T_ / TN, T_ / TM, B_ * H_), 256, SMEM_BYTES>>>(a);

    // 5. softmax rows (causal, pad to 128, tf32-rounded probs)
    softmax_rows<<<dim3(T_, B_ * H_), 256>>>(s);

    // 6. out[b,i,h*DH+d] = sum_j P[z,i,j] * vt[b, h*DH+d, j]  (K bounded)
    a = { s, 8LL * T_ * T_, (long long)T_ * T_, T_,
          vt, (long long)ND * T_, (long long)DH * T_, T_,
          out, (long long)T_ * ND, DH, ND,
          T_, H_, nullptr, 0, 1.0f, 2, 0 };
    gemm_tc<<<dim3(DH / TN, T_ / TM, B_ * H_), 256, SMEM_BYTES>>>(a);
}

// round 5
// speedup vs baseline: 4.3043x; 1.0275x over previous
#include <cuda_runtime.h>
#include <math.h>
#include <cstdint>

#define B_  4
#define T_  2048
#define DH  512
#define H_  8
#define ND  4096
#define BT  8192
#define TM  128
#define TN  128
#define KC  32
#define NSTAGE 3
#define STAGE_U32 (2 * TM * 32)              // A+B, pitch 32 floats, 8192 u32
#define SMEM_BYTES (NSTAGE * STAGE_U32 * 4)  // 98304 B

// ---------------- scratch (device globals: allocation-free) ----------------
__device__ float g_q [(size_t)BT * ND];             // tf32-rounded, k-permuted cols
__device__ float g_k [(size_t)BT * ND];
__device__ float g_vt[(size_t)B_ * ND * T_];        // [b][h*DH+d][t-perm]
__device__ float g_s [(size_t)B_ * H_ * T_ * T_];   // probs j-permuted by softmax
__device__ float g_wt[3 * (size_t)ND * DH];         // W^T, k-permuted
__device__ float g_qr[(size_t)BT * DH];             // query, k-permuted
__device__ float g_vr[(size_t)BT * DH];             // value, k-permuted

__device__ __forceinline__ int tr4(int x) { return ((x & 3) << 2) | (x >> 2); } // self-inverse
__device__ __forceinline__ uint32_t f2tf32(float x) {
    uint32_t o; asm("cvt.rna.tf32.f32 %0, %1;" : "=r"(o) : "f"(x)); return o;
}
__device__ __forceinline__ float rtf(float x) { return __uint_as_float(f2tf32(x)); }
__device__ __forceinline__ uint32_t smem_u32(const void* p) {
    uint32_t a;
    asm("{ .reg .u64 t; cvta.to.shared.u64 t, %1; cvt.u32.u64 %0, t; }" : "=r"(a) : "l"(p));
    return a;
}
__device__ __forceinline__ void cp_async16(uint32_t saddr, const float* gaddr) {
    asm volatile("cp.async.cg.shared.global [%0], [%1], 16;" :: "r"(saddr), "l"(gaddr));
}
#define CP_COMMIT() asm volatile("cp.async.commit_group;" ::: "memory")
#define CP_WAIT1()  asm volatile("cp.async.wait_group 1;" ::: "memory")
#define CP_WAIT0()  asm volatile("cp.async.wait_group 0;" ::: "memory")

__device__ __forceinline__ void mma_tf32(float& c0, float& c1, float& c2, float& c3,
                                         uint32_t a0, uint32_t a1, uint32_t a2, uint32_t a3,
                                         uint32_t b0, uint32_t b1) {
    asm volatile("mma.sync.aligned.m16n8k8.row.col.f32.tf32.tf32.f32 "
                 "{%0,%1,%2,%3}, {%4,%5,%6,%7}, {%8,%9}, {%0,%1,%2,%3};"
                 : "+f"(c0), "+f"(c1), "+f"(c2), "+f"(c3)
                 : "r"(a0), "r"(a1), "r"(a2), "r"(a3), "r"(b0), "r"(b1));
}

// ======================= generic tf32 mma.sync GEMM =======================
// C[m][n] = scale * sum_k A[m][k] * B[n][k]  (+bias); operands tf32-rounded AND
// k-permuted (tr4 within 16-groups) in gmem. permC re-permutes output columns.
struct GemmArgs {
    const float* A; long long sAz, sAh; int lda;
    const float* B; long long sBz, sBh; int ldb;
    float*       C; long long sCz, sCh; int ldc;
    int K; int zHeads;
    const float* bias; int biasMode;   // 0 none, 1 by-col, 2 by-row
    float scale;
    int causal;                        // 0 none, 1 skip tj>ti, 2 kmax=m0+TM
    int roundC;                        // round outputs to tf32
    int permC;                         // permute output cols (tr4 in 16-groups)
};

__global__ __launch_bounds__(256, 2) void gemm_tc(GemmArgs ga)
{
    const int ti = blockIdx.y, tj = blockIdx.x, z = blockIdx.z;
    if (ga.causal == 1 && tj > ti) return;

    extern __shared__ uint32_t smem[];
    const uint32_t sb = smem_u32(smem);

    const int tid  = threadIdx.x;
    const int wid  = tid >> 5, lane = tid & 31;
    const int wm   = wid >> 2, wn = wid & 3;        // 2 x 4 warp grid
    const int gid  = lane >> 2, tig = lane & 3;
    const int m0 = ti * TM, n0 = tj * TN;
    const int px = (gid & 1) << 2;                  // xor-swizzle for frag loads

    int kmax = ga.K;
    if (ga.causal == 2) kmax = min(kmax, m0 + TM);
    const int NC = kmax / KC;

    const int zb = z / ga.zHeads, zh = z - zb * ga.zHeads;
    const float* Ag = ga.A + (size_t)zb * ga.sAz + (size_t)zh * ga.sAh;
    const float* Bg = ga.B + (size_t)zb * ga.sBz + (size_t)zh * ga.sBh;

    // loader: 4 x (row=id>>3, chunk=id&7), 16B each, xor-swizzled placement
    int soff[4];
    const float *pA[4], *pB[4];
#pragma unroll
    for (int i = 0; i < 4; ++i) {
        const int id = i * 256 + tid;
        const int row = id >> 3, ch = id & 7;
        soff[i] = (row * 8 + (ch ^ ((row & 1) << 2))) * 16;
        pA[i] = Ag + (size_t)(m0 + row) * ga.lda + ch * 4;
        pB[i] = Bg + (size_t)(n0 + row) * ga.ldb + ch * 4;
    }

#define ISSUE(c) do {                                                   \
        const uint32_t _sA = sb + ((c) % NSTAGE) * (STAGE_U32 * 4);     \
        const uint32_t _sB = _sA + TM * 32 * 4;                         \
        const int _k0 = (c) * KC;                                       \
        _Pragma("unroll")                                               \
        for (int _i = 0; _i < 4; ++_i) {                                \
            cp_async16(_sA + soff[_i], pA[_i] + _k0);                   \
            cp_async16(_sB + soff[_i], pB[_i] + _k0);                   \
        }                                                               \
        CP_COMMIT();                                                    \
    } while (0)

    float acc[4][4][4];
#pragma unroll
    for (int mt = 0; mt < 4; ++mt)
#pragma unroll
        for (int nt = 0; nt < 4; ++nt)
#pragma unroll
            for (int r = 0; r < 4; ++r) acc[mt][nt][r] = 0.f;

    ISSUE(0);
    ISSUE(1);

    for (int c = 0; c < NC; ++c) {
        if (c == NC - 1) CP_WAIT0(); else CP_WAIT1();
        __syncthreads();
        if (c + 2 < NC) ISSUE(c + 2);

        const uint4* Af = (const uint4*)(smem + (c % NSTAGE) * STAGE_U32);
        const uint4* Bf = Af + TM * 8;

#pragma unroll
        for (int g = 0; g < 2; ++g) {
            const int pc = (4 * g + tig) ^ px;     // physical 16B chunk
            uint4 bf[4];
#pragma unroll
            for (int nt = 0; nt < 4; ++nt) {
                const int n = wn * 32 + nt * 8 + gid;
                bf[nt] = Bf[n * 8 + pc];
            }
#pragma unroll
            for (int mt = 0; mt < 4; ++mt) {
                const int m = wm * 64 + mt * 16 + gid;
                uint4 a0 = Af[m * 8 + pc];
                uint4 a1 = Af[(m + 8) * 8 + pc];
#pragma unroll
                for (int nt = 0; nt < 4; ++nt)
                    mma_tf32(acc[mt][nt][0], acc[mt][nt][1], acc[mt][nt][2], acc[mt][nt][3],
                             a0.x, a1.x, a0.y, a1.y, bf[nt].x, bf[nt].y);
#pragma unroll
                for (int nt = 0; nt < 4; ++nt)
                    mma_tf32(acc[mt][nt][0], acc[mt][nt][1], acc[mt][nt][2], acc[mt][nt][3],
                             a0.z, a1.z, a0.w, a1.w, bf[nt].z, bf[nt].w);
            }
        }
    }

    // ---------------- epilogue ----------------
    float* Cb = ga.C + (size_t)zb * ga.sCz + (size_t)zh * ga.sCh;
#pragma unroll
    for (int mt = 0; mt < 4; ++mt) {
        const int row0 = m0 + wm * 64 + mt * 16 + gid;
#pragma unroll
        for (int nt = 0; nt < 4; ++nt) {
            const int cl = wn * 32 + nt * 8 + tig * 2;  // local col (logical)
            float ba0 = 0.f, ba1 = 0.f, bb0 = 0.f, bb1 = 0.f;
            if (ga.biasMode == 1) {
                ba0 = bb0 = ga.bias[n0 + cl];
                ba1 = bb1 = ga.bias[n0 + cl + 1];
            } else if (ga.biasMode == 2) {
                ba0 = ba1 = ga.bias[row0];
                bb0 = bb1 = ga.bias[row0 + 8];
            }
            float v00 = acc[mt][nt][0] * ga.scale + ba0;
            float v01 = acc[mt][nt][1] * ga.scale + ba1;
            float v10 = acc[mt][nt][2] * ga.scale + bb0;
            float v11 = acc[mt][nt][3] * ga.scale + bb1;
            if (ga.roundC) { v00 = rtf(v00); v01 = rtf(v01); v10 = rtf(v10); v11 = rtf(v11); }
            float* r0 = Cb + (size_t)row0 * ga.ldc;
            float* r1 = Cb + (size_t)(row0 + 8) * ga.ldc;
            if (ga.permC) {
                const int p0 = n0 + (cl & ~15) + tr4(cl & 15);
                const int p1 = n0 + ((cl + 1) & ~15) + tr4((cl + 1) & 15);
                r0[p0] = v00; r0[p1] = v01;
                r1[p0] = v10; r1[p1] = v11;
            } else {
                *(float2*)(r0 + n0 + cl) = make_float2(v00, v01);
                *(float2*)(r1 + n0 + cl) = make_float2(v10, v11);
            }
        }
    }
#undef ISSUE
}

// ========= round + k-permute copy: out[s] = tf32(in[tr4-in-16(s)]) =========
__global__ __launch_bounds__(256) void round_perm(
    const float* __restrict__ in, float* __restrict__ out, int n4)
{
    const int i4 = blockIdx.x * 256 + threadIdx.x;
    if (i4 < n4) {
        const int s = i4 * 4;
        const int base = s & ~15, j = (s >> 2) & 3;
        float4 v;
        v.x = rtf(in[base + j]);
        v.y = rtf(in[base + 4 + j]);
        v.z = rtf(in[base + 8 + j]);
        v.w = rtf(in[base + 12 + j]);
        ((float4*)out)[i4] = v;
    }
}

// ===== W transpose + round + k-permute: Wt[n][perm(k)] = tf32(W[k][n]) =====
__global__ __launch_bounds__(256) void transpose_w(
    const float* __restrict__ W0, const float* __restrict__ W1,
    const float* __restrict__ W2, float* __restrict__ Wt)
{
    __shared__ float t[32][33];
    const float* W = (blockIdx.z == 0) ? W0 : (blockIdx.z == 1) ? W1 : W2;
    float* O = Wt + (size_t)blockIdx.z * ND * DH;
    const int x0 = blockIdx.x * 32;   // n
    const int y0 = blockIdx.y * 32;   // k
    const int tx = threadIdx.x, ty = threadIdx.y;
#pragma unroll
    for (int i = 0; i < 32; i += 8)
        t[ty + i][tx] = W[(size_t)(y0 + ty + i) * ND + x0 + tx];
    __syncthreads();
    const int kp = y0 + (tx & 16) + tr4(tx & 15);
#pragma unroll
    for (int i = 0; i < 32; i += 8)
        O[(size_t)(x0 + ty + i) * DH + kp] = rtf(t[tx][ty + i]);
}

// ============ causal softmax (pad to 128, tf32 probs, j-permuted) ============
__global__ __launch_bounds__(256) void softmax_rows(float* __restrict__ S)
{
    const int r = blockIdx.x, z = blockIdx.y;
    float* row = S + ((size_t)z * T_ + r) * T_;
    const int L = r + 1;
    const int tid = threadIdx.x;

    float v[8];
    float m = -1e30f;
#pragma unroll
    for (int it = 0; it < 8; ++it) {
        int j = tid + it * 256;
        v[it] = (j < L) ? row[j] : -1e30f;
        m = fmaxf(m, v[it]);
    }
    __shared__ float red[256];
    red[tid] = m; __syncthreads();
    for (int s = 128; s > 0; s >>= 1) {
        if (tid < s) red[tid] = fmaxf(red[tid], red[tid + s]);
        __syncthreads();
    }
    m = red[0];
    __syncthreads();

    float sum = 0.f;
#pragma unroll
    for (int it = 0; it < 8; ++it) {
        int j = tid + it * 256;
        if (j < L) { v[it] = expf(v[it] - m); sum += v[it]; }
    }
    red[tid] = sum; __syncthreads();
    for (int s = 128; s > 0; s >>= 1) {
        if (tid < s) red[tid] += red[tid + s];
        __syncthreads();
    }
    const float inv = 1.0f / red[0];

#pragma unroll
    for (int it = 0; it < 8; ++it) {
        int j = tid + it * 256;
        if (j < L) row[(j & ~15) | tr4(j & 15)] = rtf(v[it] * inv);
    }
    const int Lpad = (L + 127) & ~127;   // covers junk in diagonal 128-tile
    for (int j = L + tid; j < Lpad; j += 256) row[(j & ~15) | tr4(j & 15)] = 0.f;
}

// =====================================================================
extern "C" void kernel_launch(void* const* d_in, const int* in_sizes, int n_in,
                              void* d_out, int out_size)
{
    const float* query = (const float*)d_in[0];
    const float* value = (const float*)d_in[1];
    const float* Wq    = (const float*)d_in[2];
    const float* bq    = (const float*)d_in[3];
    const float* Wk    = (const float*)d_in[4];
    const float* bk    = (const float*)d_in[5];
    const float* Wv    = (const float*)d_in[6];
    const float* bv    = (const float*)d_in[7];
    float* out = (float*)d_out;

    float *q, *k, *vt, *s, *wt, *qr, *vr;
    cudaGetSymbolAddress((void**)&q,  g_q);
    cudaGetSymbolAddress((void**)&k,  g_k);
    cudaGetSymbolAddress((void**)&vt, g_vt);
    cudaGetSymbolAddress((void**)&s,  g_s);
    cudaGetSymbolAddress((void**)&wt, g_wt);
    cudaGetSymbolAddress((void**)&qr, g_qr);
    cudaGetSymbolAddress((void**)&vr, g_vr);

    cudaFuncSetAttribute(gemm_tc, cudaFuncAttributeMaxDynamicSharedMemorySize, SMEM_BYTES);

    // 0. pre-round + k-permute inputs; transpose + round + permute weights
    const int n4 = BT * DH / 4;
    round_perm<<<n4 / 256, 256>>>(query, qr, n4);
    round_perm<<<n4 / 256, 256>>>(value, vr, n4);
    transpose_w<<<dim3(ND / 32, DH / 32, 3), dim3(32, 8)>>>(Wq, Wk, Wv, wt);

    GemmArgs a;

    // 1. q = query @ Wq + bq   (rounded, col-permuted out)
    a = { qr, 0, 0, DH,
          wt + 0 * (size_t)ND * DH, 0, 0, DH,
          q, 0, 0, ND,
          DH, 1, bq, 1, 1.0f, 0, 1, 1 };
    gemm_tc<<<dim3(ND / TN, BT / TM, 1), 256, SMEM_BYTES>>>(a);

    // 2. k = value @ Wk + bk   (rounded, col-permuted out)
    a = { vr, 0, 0, DH,
          wt + 1 * (size_t)ND * DH, 0, 0, DH,
          k, 0, 0, ND,
          DH, 1, bk, 1, 1.0f, 0, 1, 1 };
    gemm_tc<<<dim3(ND / TN, BT / TM, 1), 256, SMEM_BYTES>>>(a);

    // 3. vt[b][m][t] = (Wv^T @ value_b^T) + bv[m]   (rounded, t-permuted out)
    a = { wt + 2 * (size_t)ND * DH, 0, 0, DH,
          vr, (long long)T_ * DH, 0, DH,
          vt, (long long)ND * T_, 0, T_,
          DH, 1, bv, 2, 1.0f, 0, 1, 1 };
    gemm_tc<<<dim3(T_ / TN, ND / TM, B_), 256, SMEM_BYTES>>>(a);

    // 4. scores = scale * q @ k^T   (causal tile skip; plain output order)
    a = { q, (long long)T_ * ND, DH, ND,
          k, (long long)T_ * ND, DH, ND,
          s, 8LL * T_ * T_, (long long)T_ * T_, T_,
          DH, H_, nullptr, 0, 0.044194173824159216f, 1, 0, 0 };
    gemm_tc<<<dim3(T_ / TN, T_ / TM, B_ * H_), 256, SMEM_BYTES>>>(a);

    // 5. softmax (causal, pad to 128, writes j-permuted tf32 probs)
    softmax_rows<<<dim3(T_, B_ * H_), 256>>>(s);

    // 6. out = P @ V   (K bounded at m0+128; plain output)
    a = { s, 8LL * T_ * T_, (long long)T_ * T_, T_,
          vt, (long long)ND * T_, (long long)DH * T_, T_,
          out, (long long)T_ * ND, DH, ND,
          T_, H_, nullptr, 0, 1.0f, 2, 0, 0 };
    gemm_tc<<<dim3(DH / TN, T_ / TM, B_ * H_), 256, SMEM_BYTES>>>(a);
}